// round 15
// baseline (speedup 1.0000x reference)
#include <cuda_runtime.h>

#define NN 2048
#define EE 65536
#define SEQL 5
#define IND 32
#define HID 64
#define OUTD 16

typedef unsigned long long ull;

// ---------------- scratch (device globals; no allocs allowed) ----------------
__device__ float d_deg[NN];
__device__ float d_dinv[NN];
__device__ float d_dself[NN];
__device__ int   d_count[NN];
__device__ int   d_cursor[NN];
__device__ int   d_rowptr[NN + 1];
__device__ int   d_csr_src[EE];
__device__ float d_csr_w[EE];
__device__ float d_Wz[IND * HID], d_Wh[IND * HID];            // folded gate weights
__device__ float d_bz[HID], d_bh[HID];
__device__ __align__(16) float d_emb[NN * HID];
__device__ __align__(16) float d_r1[NN * HID];
__device__ __align__(16) float d_av[NN * HID];                // emb@Wi1[:64]+bi1
__device__ __align__(16) float d_bv[NN * HID];                // emb@Wi1[64:]

// ---------------- software grid barrier (sense-reversing) --------------------
// Safe because: (a) all blocks of the calling grid are provably co-resident,
// (b) sense is read BEFORE arrival (flip needs ALL arrivals, so pre-read sense
// can't be stale), (c) sense increments monotonically -> consistent across
// graph replays, (d) cnt returns to 0 after every barrier.
__device__ int g_bar_cnt = 0;
__device__ int g_bar_sense = 0;

__device__ __forceinline__ void grid_bar(int nblocks) {
    __syncthreads();
    if (threadIdx.x == 0) {
        int s = *(volatile int*)&g_bar_sense;       // read sense BEFORE arriving
        __threadfence();                            // flush my block's writes
        if (atomicAdd(&g_bar_cnt, 1) == nblocks - 1) {
            g_bar_cnt = 0;
            __threadfence();
            atomicAdd(&g_bar_sense, 1);             // release everyone
        } else {
            while (*(volatile int*)&g_bar_sense == s) { }
        }
        __threadfence();                            // acquire others' writes
    }
    __syncthreads();
}

// ---------------- f32x2 packed helpers (Blackwell double-rate fp32) ----------
__device__ __forceinline__ ull f2_add(ull a, ull b) {
    ull r; asm("add.rn.f32x2 %0,%1,%2;" : "=l"(r) : "l"(a), "l"(b)); return r;
}
__device__ __forceinline__ ull f2_fma(ull a, ull b, ull c) {
    ull r; asm("fma.rn.f32x2 %0,%1,%2,%3;" : "=l"(r) : "l"(a), "l"(b), "l"(c)); return r;
}
__device__ __forceinline__ ull f2_relu(ull a) {
    float lo, hi;
    asm("mov.b64 {%0,%1},%2;" : "=f"(lo), "=f"(hi) : "l"(a));
    lo = fmaxf(lo, 0.f); hi = fmaxf(hi, 0.f);
    ull r; asm("mov.b64 %0,{%1,%2};" : "=l"(r) : "f"(lo), "f"(hi)); return r;
}

// ============================================================================
// k_pre (64 blocks x 1024 threads = 1 thread per edge, software grid barriers):
//   zero -> bar -> deg/count atomics -> bar -> block-0 scan -> bar ->
//   scatter (edge kept in registers) + gate-weight fold
// ============================================================================
__global__ void __launch_bounds__(1024) k_pre(
        const int* __restrict__ ei, const float* __restrict__ ew,
        const float* __restrict__ Wcz, const float* __restrict__ bcz,
        const float* __restrict__ Wlz, const float* __restrict__ blz,
        const float* __restrict__ Wch, const float* __restrict__ bch,
        const float* __restrict__ Wlh, const float* __restrict__ blh) {
    const int NB = 64;
    int tid = blockIdx.x * 1024 + threadIdx.x;          // 0..EE-1

    // phase 0: zero deg/count
    if (tid < NN) { d_deg[tid] = 0.0f; d_count[tid] = 0; }
    grid_bar(NB);

    // phase A: load my edge once; count + weighted degree
    int src = ei[tid];
    int dst = ei[EE + tid];
    float w = ew[tid];
    atomicAdd(&d_deg[dst], w);
    atomicAdd(&d_count[dst], 1);
    grid_bar(NB);

    // phase B: block 0 computes dinv/dself + inclusive scan -> rowptr, cursor
    if (blockIdx.x == 0) {
        int t = threadIdx.x;
        __shared__ int s[NN];
        for (int i = t; i < NN; i += 1024) {
            float di = rsqrtf(d_deg[i] + 1.0f);        // +1 self-loop
            d_dinv[i] = di; d_dself[i] = di * di;
            s[i] = d_count[i];
        }
        __syncthreads();
        for (int off = 1; off < NN; off <<= 1) {
            int i1 = t + 1024;
            int v0 = (t >= off)  ? s[t - off]  : 0;
            int v1 = (i1 >= off) ? s[i1 - off] : 0;
            __syncthreads();
            s[t] += v0; s[i1] += v1;
            __syncthreads();
        }
        d_rowptr[t + 1] = s[t];
        d_rowptr[t + 1025] = s[t + 1024];
        d_cursor[t + 1] = s[t];
        if (t < 1023) d_cursor[t + 1025] = s[t + 1024];
        if (t == 0) { d_rowptr[0] = 0; d_cursor[0] = 0; }
    }
    grid_bar(NB);

    // phase C: scatter (edge still in registers) + independent weight fold
    int pos = atomicAdd(&d_cursor[dst], 1);
    d_csr_src[pos] = src;
    d_csr_w[pos] = d_dinv[src] * w * d_dinv[dst];

    if (tid < IND * HID) {                              // folded gate weights
        int i = tid >> 6, j = tid & 63;
        float a0 = 0.f, a1 = 0.f, h0 = 0.f, h1 = 0.f;
#pragma unroll 8
        for (int k = 0; k < HID; k += 2) {
            a0 += Wcz[i * HID + k]     * Wlz[k * HID + j];
            a1 += Wcz[i * HID + k + 1] * Wlz[(k + 1) * HID + j];
            h0 += Wch[i * HID + k]     * Wlh[k * HID + j];
            h1 += Wch[i * HID + k + 1] * Wlh[(k + 1) * HID + j];
        }
        d_Wz[tid] = a0 + a1; d_Wh[tid] = h0 + h1;
    }
    if (tid < HID) {
        float bz = blz[tid], bh = blh[tid];
#pragma unroll 4
        for (int k = 0; k < HID; k++) {
            bz += bcz[k] * Wlz[k * HID + tid];
            bh += bch[k] * Wlh[k * HID + tid];
        }
        d_bz[tid] = bz; d_bh[tid] = bh;
    }
}

// ============================================================================
// k_main (2048 blocks x 64 threads, block n = node n, software grid barriers).
// __launch_bounds__(64, 16): regs capped so >=16 blocks/SM -> capacity
// 148*16 = 2368 >= 2048 -> whole grid co-resident in wave 1 -> barrier safe.
//   node: spmm1(x,160) -> gates -> emb -> av/bv
//   bar -> gcn1: spmm64(emb) -> @Wc1 -> LN -> relu -> r1
//   bar -> gcn2: spmm64(r1) -> @Wc2 -> LN -> relu -> @Wout -> node_pred
// ============================================================================
__global__ void __launch_bounds__(64, 16) k_main(
        const float* __restrict__ x,
        const float* __restrict__ Wred, const float* __restrict__ bred,
        const float* __restrict__ Wi1,  const float* __restrict__ bi1,
        const float* __restrict__ Wc1,  const float* __restrict__ bc1,
        const float* __restrict__ g1,   const float* __restrict__ be1,
        const float* __restrict__ Wc2,  const float* __restrict__ bc2,
        const float* __restrict__ g2,   const float* __restrict__ be2,
        const float* __restrict__ Wout, const float* __restrict__ bout,
        float* __restrict__ outp) {
    int n = blockIdx.x, j = threadIdx.x;
    int c = j & 31, th = j >> 5;                        // th in {0,1} (warp id)
    __shared__ int   ss[64];
    __shared__ float swt[64];
    __shared__ float spm[SEQL * IND];
    __shared__ float sh[SEQL * HID];
    __shared__ float sa[HID];
    __shared__ float sr[HID];
    __shared__ float rbuf[4];

    int r0 = d_rowptr[n], r1 = d_rowptr[n + 1];
    float ds = d_dself[n];

    // ---- node phase: spmm1, thread j covers timesteps th, th+2 (+4 if th==0)
    {
        const float* xb0 = x + (th + 0) * NN * IND + c;
        const float* xb1 = x + (th + 2) * NN * IND + c;
        const float* xb2 = x + 4 * NN * IND + c;        // only th==0 uses
        bool v2 = (th == 0);                            // warp-uniform
        float a0 = ds * xb0[n * IND];
        float a1 = ds * xb1[n * IND];
        float a2 = v2 ? ds * xb2[n * IND] : 0.f;
        for (int base = r0; base < r1; base += 64) {
            int m = min(64, r1 - base);
            if (j < m) { ss[j] = d_csr_src[base + j]; swt[j] = d_csr_w[base + j]; }
            __syncthreads();
            int k = 0;
            for (; k + 2 <= m; k += 2) {                // up to 6 gathers in flight
                int s0 = ss[k] * IND, s1 = ss[k + 1] * IND;
                float w0 = swt[k], w1 = swt[k + 1];
                a0 += w0 * xb0[s0];
                a1 += w0 * xb1[s0];
                if (v2) a2 += w0 * xb2[s0];
                a0 += w1 * xb0[s1];
                a1 += w1 * xb1[s1];
                if (v2) a2 += w1 * xb2[s1];
            }
            for (; k < m; k++) {
                int s0 = ss[k] * IND; float w0 = swt[k];
                a0 += w0 * xb0[s0];
                a1 += w0 * xb1[s0];
                if (v2) a2 += w0 * xb2[s0];
            }
            __syncthreads();
        }
        spm[th * IND + c] = a0;
        spm[(th + 2) * IND + c] = a1;
        if (v2) spm[4 * IND + c] = a2;
    }
    __syncthreads();

    // ---- gates: 5 outputs per thread (t = 0..4, channel j)
    {
        float bzj = d_bz[j], bhj = d_bh[j];
#pragma unroll
        for (int q = 0; q < SEQL; q++) {
            float az = bzj, ah = bhj;
#pragma unroll
            for (int k = 0; k < IND; k++) {
                float pv = spm[q * IND + k];
                az += pv * d_Wz[k * HID + j];
                ah += pv * d_Wh[k * HID + j];
            }
            float zg = 1.f / (1.f + expf(-az));
            sh[q * HID + j] = (1.f - zg) * tanhf(ah);
        }
    }
    __syncthreads();

    // ---- emb = sh @ Wred + bred
    {
        float b0 = bred[j], b1 = 0.f, b2 = 0.f, b3 = 0.f;
#pragma unroll 4
        for (int k = 0; k < SEQL * HID; k += 4) {
            b0 += sh[k + 0] * Wred[(k + 0) * HID + j];
            b1 += sh[k + 1] * Wred[(k + 1) * HID + j];
            b2 += sh[k + 2] * Wred[(k + 2) * HID + j];
            b3 += sh[k + 3] * Wred[(k + 3) * HID + j];
        }
        float e = (b0 + b1) + (b2 + b3);
        d_emb[n * HID + j] = e;
        sa[j] = e;                                     // reuse sa as emb cache
    }
    __syncthreads();

    // ---- av/bv for the interaction predictor
    {
        float aa = bi1[j], bb = 0.f;
#pragma unroll 4
        for (int k = 0; k < HID; k++) {
            float e = sa[k];
            aa += e * Wi1[k * HID + j];
            bb += e * Wi1[(HID + k) * HID + j];
        }
        d_av[n * HID + j] = aa;
        d_bv[n * HID + j] = bb;
    }
    grid_bar(NN);                                      // all emb visible

    // ---- gcn1: spmm64(emb) -> @Wc1 -> LN -> relu -> d_r1
    {
        float a0 = ds * d_emb[n * HID + j];
        float a1 = 0.f, a2 = 0.f, a3 = 0.f;
        for (int base = r0; base < r1; base += 64) {
            int m = min(64, r1 - base);
            if (j < m) { ss[j] = d_csr_src[base + j]; swt[j] = d_csr_w[base + j]; }
            __syncthreads();
            int k = 0;
            for (; k + 4 <= m; k += 4) {
                a0 += swt[k + 0] * d_emb[ss[k + 0] * HID + j];
                a1 += swt[k + 1] * d_emb[ss[k + 1] * HID + j];
                a2 += swt[k + 2] * d_emb[ss[k + 2] * HID + j];
                a3 += swt[k + 3] * d_emb[ss[k + 3] * HID + j];
            }
            for (; k < m; k++) a0 += swt[k] * d_emb[ss[k] * HID + j];
            __syncthreads();
        }
        sa[j] = (a0 + a1) + (a2 + a3);
        __syncthreads();
        float h = bc1[j];
#pragma unroll
        for (int k = 0; k < HID; k++) h += sa[k] * Wc1[k * HID + j];
        float v = h;
#pragma unroll
        for (int o = 16; o > 0; o >>= 1) v += __shfl_xor_sync(0xffffffffu, v, o);
        if ((j & 31) == 0) rbuf[j >> 5] = v;
        __syncthreads();
        float mu = (rbuf[0] + rbuf[1]) * (1.f / 64.f);
        float d = h - mu;
        float v2 = d * d;
#pragma unroll
        for (int o = 16; o > 0; o >>= 1) v2 += __shfl_xor_sync(0xffffffffu, v2, o);
        if ((j & 31) == 0) rbuf[(j >> 5) + 2] = v2;
        __syncthreads();
        float var = (rbuf[2] + rbuf[3]) * (1.f / 64.f);
        d_r1[n * HID + j] = fmaxf(0.f, d * rsqrtf(var + 1e-5f) * g1[j] + be1[j]);
    }
    grid_bar(NN);                                      // all r1 visible

    // ---- gcn2: spmm64(r1) -> @Wc2 -> LN -> relu -> @Wout -> node_pred
    {
        float a0 = ds * d_r1[n * HID + j];
        float a1 = 0.f, a2 = 0.f, a3 = 0.f;
        for (int base = r0; base < r1; base += 64) {
            int m = min(64, r1 - base);
            if (j < m) { ss[j] = d_csr_src[base + j]; swt[j] = d_csr_w[base + j]; }
            __syncthreads();
            int k = 0;
            for (; k + 4 <= m; k += 4) {
                a0 += swt[k + 0] * d_r1[ss[k + 0] * HID + j];
                a1 += swt[k + 1] * d_r1[ss[k + 1] * HID + j];
                a2 += swt[k + 2] * d_r1[ss[k + 2] * HID + j];
                a3 += swt[k + 3] * d_r1[ss[k + 3] * HID + j];
            }
            for (; k < m; k++) a0 += swt[k] * d_r1[ss[k] * HID + j];
            __syncthreads();
        }
        sa[j] = (a0 + a1) + (a2 + a3);
        __syncthreads();
        float h = bc2[j];
#pragma unroll
        for (int k = 0; k < HID; k++) h += sa[k] * Wc2[k * HID + j];
        float v = h;
#pragma unroll
        for (int o = 16; o > 0; o >>= 1) v += __shfl_xor_sync(0xffffffffu, v, o);
        if ((j & 31) == 0) rbuf[j >> 5] = v;
        __syncthreads();
        float mu = (rbuf[0] + rbuf[1]) * (1.f / 64.f);
        float d = h - mu;
        float v2 = d * d;
#pragma unroll
        for (int o = 16; o > 0; o >>= 1) v2 += __shfl_xor_sync(0xffffffffu, v2, o);
        if ((j & 31) == 0) rbuf[(j >> 5) + 2] = v2;
        __syncthreads();
        float var = (rbuf[2] + rbuf[3]) * (1.f / 64.f);
        float r = fmaxf(0.f, d * rsqrtf(var + 1e-5f) * g2[j] + be2[j]);
        sr[j] = r;
        __syncthreads();
        if (j < OUTD) {
            float o = bout[j];
#pragma unroll
            for (int k = 0; k < HID; k++) o += sr[k] * Wout[k * OUTD + j];
            outp[n * OUTD + j] = o;
        }
    }
}

// ---------------- scores: relu(a_i + b_j) . w  (f32x2 packed) ----------------
// Pipe-balanced: fma pipe (add2+fma2) == alu pipe (2x FMNMX) per pair.
__global__ void __launch_bounds__(256) k_scores(const float* __restrict__ Wi2,
                                                const float* __restrict__ bi2,
                                                float* __restrict__ outp) {
    __shared__ __align__(16) float sA[64][66];
    __shared__ __align__(16) float sB[64][66];
    __shared__ __align__(16) float sW[64];
    int tx = threadIdx.x, ty = threadIdx.y;
    int tid = ty * 16 + tx;
    int i0 = blockIdx.y * 64, j0 = blockIdx.x * 64;
    for (int f = tid; f < 64 * 32; f += 256) {
        int r = f >> 5, c2 = f & 31;
        float2 va = *(const float2*)&d_av[(i0 + r) * HID + 2 * c2];
        float2 vb = *(const float2*)&d_bv[(j0 + r) * HID + 2 * c2];
        *(float2*)&sA[r][2 * c2] = va;
        *(float2*)&sB[r][2 * c2] = vb;
    }
    if (tid < 64) sW[tid] = Wi2[tid];
    __syncthreads();

    ull acc[4][4];
#pragma unroll
    for (int r = 0; r < 4; r++)
#pragma unroll
        for (int c = 0; c < 4; c++) acc[r][c] = 0ull;

#pragma unroll 4
    for (int h = 0; h < 32; h++) {
        ull w2 = *(const ull*)&sW[2 * h];
        ull A[4], B[4];
#pragma unroll
        for (int r = 0; r < 4; r++) A[r] = *(const ull*)&sA[ty * 4 + r][2 * h];
#pragma unroll
        for (int c = 0; c < 4; c++) B[c] = *(const ull*)&sB[tx * 4 + c][2 * h];
#pragma unroll
        for (int r = 0; r < 4; r++)
#pragma unroll
            for (int c = 0; c < 4; c++) {
                ull t = f2_add(A[r], B[c]);
                t = f2_relu(t);
                acc[r][c] = f2_fma(t, w2, acc[r][c]);
            }
    }

    float bb = bi2[0];
    float* sc = outp + NN * OUTD;
#pragma unroll
    for (int r = 0; r < 4; r++) {
        float4 o;
        float res[4];
#pragma unroll
        for (int c = 0; c < 4; c++) {
            float lo, hi;
            asm("mov.b64 {%0,%1},%2;" : "=f"(lo), "=f"(hi) : "l"(acc[r][c]));
            res[c] = lo + hi + bb;
        }
        o.x = res[0]; o.y = res[1]; o.z = res[2]; o.w = res[3];
        *(float4*)&sc[(i0 + ty * 4 + r) * NN + j0 + tx * 4] = o;
    }
}

// ---------------- launcher ----------------------------------------------------
extern "C" void kernel_launch(void* const* d_in, const int* in_sizes, int n_in,
                              void* d_out, int out_size) {
    (void)out_size;
    const float* x = nullptr;
    const int* ei = nullptr;
    const float* ew = nullptr;
    const float* W[28];
    int wi = 0;
    for (int i = 0; i < n_in; i++) {
        int s = in_sizes[i];
        if (s == SEQL * NN * IND)      x  = (const float*)d_in[i];
        else if (s == 2 * EE)          ei = (const int*)d_in[i];
        else if (s == EE)              ew = (const float*)d_in[i];
        else if (wi < 28)              W[wi++] = (const float*)d_in[i];
    }
    const float *Wcz = W[0],  *bcz = W[1],  *Wlz = W[2],  *blz = W[3];
    const float *Wch = W[8],  *bch = W[9],  *Wlh = W[10], *blh = W[11];
    const float *Wred = W[12], *bred = W[13];
    const float *Wc1 = W[14], *bc1 = W[15], *Wc2 = W[16], *bc2 = W[17];
    const float *g1 = W[18],  *be1 = W[19], *g2 = W[20],  *be2 = W[21];
    const float *Wout = W[22], *bout = W[23];
    const float *Wi1 = W[24], *bi1 = W[25], *Wi2 = W[26], *bi2 = W[27];
    float* outp = (float*)d_out;

    k_pre<<<64, 1024>>>(ei, ew, Wcz, bcz, Wlz, blz, Wch, bch, Wlh, blh);
    k_main<<<NN, 64>>>(x, Wred, bred, Wi1, bi1, Wc1, bc1, g1, be1,
                       Wc2, bc2, g2, be2, Wout, bout, outp);
    k_scores<<<dim3(NN / 64, NN / 64), dim3(16, 16)>>>(Wi2, bi2, outp);
}